// round 5
// baseline (speedup 1.0000x reference)
#include <cuda_runtime.h>

#define TAB 4096
#define FULLMASK 0xffffffffu
typedef unsigned long long ull;

__device__ float g_htab[2][TAB * 128];

__device__ __forceinline__ float silu_f(float x) { return __fdividef(x, 1.0f + __expf(-x)); }
__device__ __forceinline__ ull dup2(float x) {
    ull r; unsigned u = __float_as_uint(x);
    asm("mov.b64 %0, {%1,%1};" : "=l"(r) : "r"(u)); return r;
}
__device__ __forceinline__ void fma2(ull &d, ull a, ull b) {
    asm("fma.rn.f32x2 %0, %1, %2, %0;" : "+l"(d) : "l"(a), "l"(b));
}
__device__ __forceinline__ void unpack2(ull v, float &lo, float &hi) {
    unsigned a, b; asm("mov.b64 {%0,%1}, %2;" : "=r"(a), "=r"(b) : "l"(v));
    lo = __uint_as_float(a); hi = __uint_as_float(b);
}

// ---------------------------------------------------------------------------
// Length -> h(128) lookup table builder. Thread f owns feature f; w2 column f
// cached in registers, h1 shared via smem. blockIdx.y selects filter.
// ---------------------------------------------------------------------------
__global__ void __launch_bounds__(128) build_tab_kernel(
    const float* __restrict__ w1a, const float* __restrict__ b1a,
    const float* __restrict__ w2a, const float* __restrict__ b2a,
    const float* __restrict__ w1b, const float* __restrict__ b1b,
    const float* __restrict__ w2b, const float* __restrict__ b2b,
    int rows_per_block)
{
    int filt = blockIdx.y;
    const float* w1 = filt ? w1b : w1a; const float* b1 = filt ? b1b : b1a;
    const float* w2 = filt ? w2b : w2a; const float* b2 = filt ? b2b : b2a;
    __shared__ float h1s[128];
    int f = threadIdx.x;
    float wcol[128], w1col[32];
#pragma unroll
    for (int k = 0; k < 128; k++) wcol[k] = __ldg(&w2[k * 128 + f]);
#pragma unroll
    for (int k = 0; k < 32; k++) w1col[k] = __ldg(&w1[k * 128 + f]);
    float b1f = __ldg(&b1[f]), b2f = __ldg(&b2[f]);
    const float step  = 5.0f / 31.0f;
    const float gamma = 0.5f / (step * step);
    const float dx    = 5.0f / (float)(TAB - 1);
    int r0 = blockIdx.x * rows_per_block;
    for (int rr = 0; rr < rows_per_block; rr++) {
        int row = r0 + rr;
        float x = (float)row * dx;
        float a1 = b1f;
#pragma unroll
        for (int k = 0; k < 32; k++) {
            float d = x - (float)k * step;
            a1 = fmaf(__expf(-gamma * d * d), w1col[k], a1);
        }
        h1s[f] = silu_f(a1);
        __syncthreads();
        float a2 = b2f;
#pragma unroll
        for (int k = 0; k < 128; k++) a2 = fmaf(h1s[k], wcol[k], a2);
        g_htab[filt][(size_t)row * 128 + f] = silu_f(a2);
        __syncthreads();
    }
}

// ---------------------------------------------------------------------------
// Node kernel: t = [2*inv | so3(2*ev)] @ w_int + b_int
// out1 = 2*inv + t[:,:128]; out2 = 2*ev * (1 + t[:,128:][seg]).
// Warp handles a node pair; w_int read via __ldg (L1-resident, shared by pair).
// ---------------------------------------------------------------------------
__global__ void __launch_bounds__(256) node_kernel(
    const float* __restrict__ invf, const float* __restrict__ evf,
    const float* __restrict__ w_int, const float* __restrict__ b_int,
    float* __restrict__ out1, float* __restrict__ out2, int N)
{
    __shared__ float xs[8][2][136];
    int warp = threadIdx.x >> 5, lane = threadIdx.x & 31;
    int nwarps = gridDim.x * 8;
    int npairs = (N + 1) >> 1;
    int o4 = (lane < 4) ? (128 + lane) : lane;
    float b0 = __ldg(b_int + lane),      b1v = __ldg(b_int + 32 + lane);
    float b2v = __ldg(b_int + 64 + lane), b3v = __ldg(b_int + 96 + lane);
    float b4v = __ldg(b_int + o4);

    for (int pr = blockIdx.x * 8 + warp; pr < npairs; pr += nwarps) {
        int n0 = pr * 2;
        int n1 = (n0 + 1 < N) ? (n0 + 1) : n0;
        float attv[2];
#pragma unroll
        for (int nd = 0; nd < 2; nd++) {
            int n = nd ? n1 : n0;
            float* X = xs[warp][nd];
#pragma unroll
            for (int j = 0; j < 4; j++)
                X[lane + 32 * j] = 2.0f * __ldg(invf + (size_t)n * 128 + lane + 32 * j);
            float av = 0.f, dsq = 0.f;
            if (lane < 16) { av = 2.0f * __ldg(evf + (size_t)n * 16 + lane); dsq = av * av; }
            attv[nd] = av;
            float v0 = __shfl_sync(FULLMASK, dsq, 0);
            float v1 = __shfl_sync(FULLMASK, dsq, 1) + __shfl_sync(FULLMASK, dsq, 2)
                     + __shfl_sync(FULLMASK, dsq, 3);
            float v2 = __shfl_sync(FULLMASK, dsq, 4) + __shfl_sync(FULLMASK, dsq, 5)
                     + __shfl_sync(FULLMASK, dsq, 6) + __shfl_sync(FULLMASK, dsq, 7)
                     + __shfl_sync(FULLMASK, dsq, 8);
            float v3 = __shfl_sync(FULLMASK, dsq, 9) + __shfl_sync(FULLMASK, dsq, 10)
                     + __shfl_sync(FULLMASK, dsq, 11) + __shfl_sync(FULLMASK, dsq, 12)
                     + __shfl_sync(FULLMASK, dsq, 13) + __shfl_sync(FULLMASK, dsq, 14)
                     + __shfl_sync(FULLMASK, dsq, 15);
            if (lane == 0) { X[128] = v0; X[129] = v1; X[130] = v2; X[131] = v3; }
        }
        __syncwarp();

        float a00 = b0, a01 = b1v, a02 = b2v, a03 = b3v, a04 = b4v;
        float a10 = b0, a11 = b1v, a12 = b2v, a13 = b3v, a14 = b4v;
        const float* x0 = xs[warp][0];
        const float* x1 = xs[warp][1];
#pragma unroll 4
        for (int i = 0; i < 132; i++) {
            float xa = x0[i], xb = x1[i];
            const float* wr = w_int + i * 132;
            float w0 = __ldg(wr + lane),      w1 = __ldg(wr + 32 + lane);
            float w2 = __ldg(wr + 64 + lane), w3 = __ldg(wr + 96 + lane);
            float w4 = __ldg(wr + o4);
            a00 = fmaf(xa, w0, a00); a01 = fmaf(xa, w1, a01);
            a02 = fmaf(xa, w2, a02); a03 = fmaf(xa, w3, a03); a04 = fmaf(xa, w4, a04);
            a10 = fmaf(xb, w0, a10); a11 = fmaf(xb, w1, a11);
            a12 = fmaf(xb, w2, a12); a13 = fmaf(xb, w3, a13); a14 = fmaf(xb, w4, a14);
        }
        // node 0
        out1[(size_t)n0 * 128 + lane]      = x0[lane] + a00;
        out1[(size_t)n0 * 128 + 32 + lane] = x0[32 + lane] + a01;
        out1[(size_t)n0 * 128 + 64 + lane] = x0[64 + lane] + a02;
        out1[(size_t)n0 * 128 + 96 + lane] = x0[96 + lane] + a03;
        {
            float c0 = __shfl_sync(FULLMASK, a04, 0), c1 = __shfl_sync(FULLMASK, a04, 1);
            float c2 = __shfl_sync(FULLMASK, a04, 2), c3 = __shfl_sync(FULLMASK, a04, 3);
            if (lane < 16) {
                float bs = (lane == 0) ? c0 : ((lane < 4) ? c1 : ((lane < 9) ? c2 : c3));
                out2[(size_t)n0 * 16 + lane] = attv[0] * (1.0f + bs);
            }
        }
        // node 1
        if (n1 != n0) {
            out1[(size_t)n1 * 128 + lane]      = x1[lane] + a10;
            out1[(size_t)n1 * 128 + 32 + lane] = x1[32 + lane] + a11;
            out1[(size_t)n1 * 128 + 64 + lane] = x1[64 + lane] + a12;
            out1[(size_t)n1 * 128 + 96 + lane] = x1[96 + lane] + a13;
            float c0 = __shfl_sync(FULLMASK, a14, 0), c1 = __shfl_sync(FULLMASK, a14, 1);
            float c2 = __shfl_sync(FULLMASK, a14, 2), c3 = __shfl_sync(FULLMASK, a14, 3);
            if (lane < 16) {
                float bs = (lane == 0) ? c0 : ((lane < 4) ? c1 : ((lane < 9) ? c2 : c3));
                out2[(size_t)n1 * 16 + lane] = attv[1] * (1.0f + bs);
            }
        }
        __syncwarp();
    }
}

// ---------------------------------------------------------------------------
// Edge kernel. blockIdx.y selects filter net. Warp handles 8 edges per pass.
// fw[e] = table_lerp(length) + silu(silu(inv4 @ w1 + b1) @ w2 + b2).
// Layer-2 GEMM uses fma.rn.f32x2 over edge pairs.
// ---------------------------------------------------------------------------
__global__ void __launch_bounds__(256) edge_kernel(
    const float* __restrict__ evf, const int* __restrict__ senders,
    const int* __restrict__ receivers, const float* __restrict__ lengths,
    const float* __restrict__ fi_w1, const float* __restrict__ fi_b1,
    const float* __restrict__ fi_w2, const float* __restrict__ fi_b2,
    const float* __restrict__ fe_w1, const float* __restrict__ fe_b1,
    const float* __restrict__ fe_w2, const float* __restrict__ fe_b2,
    float* __restrict__ fwi, float* __restrict__ fwe, int E)
{
    int filt = blockIdx.y;
    const float* we1 = filt ? fe_w1 : fi_w1; const float* be1 = filt ? fe_b1 : fi_b1;
    const float* we2 = filt ? fe_w2 : fi_w2; const float* be2 = filt ? fe_b2 : fi_b2;
    float* outp = filt ? fwe : fwi;
    const float* tab = g_htab[filt];

    __shared__ __align__(16) float s_we2[4096];
    __shared__ float2 s_e1[8][4][32];
    __shared__ float s_ed[8][8][5];
    __shared__ int s_ti[8][8];

    int tid = threadIdx.x;
    for (int i = tid; i < 4096; i += 256) s_we2[i] = we2[i];
    __syncthreads();

    int warp = tid >> 5, lane = tid & 31;
    // hoisted per-lane constants
    float w1l0 = __ldg(we1 + lane),      w1l1 = __ldg(we1 + 32 + lane);
    float w1l2 = __ldg(we1 + 64 + lane), w1l3 = __ldg(we1 + 96 + lane);
    float bl   = __ldg(be1 + lane);
    float4 bb  = __ldg(reinterpret_cast<const float4*>(be2) + lane);
    ull bd0 = dup2(bb.x), bd1 = dup2(bb.y), bd2 = dup2(bb.z), bd3 = dup2(bb.w);
    const float tscale = (float)(TAB - 1) / 5.0f;
    const float4* wv = reinterpret_cast<const float4*>(s_we2);
    const float4* tabv = reinterpret_cast<const float4*>(tab);
    float4* outv = reinterpret_cast<float4*>(outp);

    int gw = blockIdx.x * 8 + warp;
    int nwarps = gridDim.x * 8;

    for (int base = gw * 8; base < E; base += nwarps * 8) {
        // gather: lanes 0..7 each own an edge
        if (lane < 8) {
            int e = base + lane; if (e >= E) e = E - 1;
            int sN = __ldg(senders + e), rN = __ldg(receivers + e);
            const float4* As = reinterpret_cast<const float4*>(evf) + (size_t)sN * 4;
            const float4* Ar = reinterpret_cast<const float4*>(evf) + (size_t)rN * 4;
            float4 a, b; float dx, dy, dz, dw;
            float i0, i1, i2, i3;
            a = As[0]; b = Ar[0]; dx = a.x-b.x; dy = a.y-b.y; dz = a.z-b.z; dw = a.w-b.w;
            i0 = dx*dx; i1 = dy*dy + dz*dz + dw*dw;
            a = As[1]; b = Ar[1]; dx = a.x-b.x; dy = a.y-b.y; dz = a.z-b.z; dw = a.w-b.w;
            i2 = dx*dx + dy*dy + dz*dz + dw*dw;
            a = As[2]; b = Ar[2]; dx = a.x-b.x; dy = a.y-b.y; dz = a.z-b.z; dw = a.w-b.w;
            i2 += dx*dx; i3 = dy*dy + dz*dz + dw*dw;
            a = As[3]; b = Ar[3]; dx = a.x-b.x; dy = a.y-b.y; dz = a.z-b.z; dw = a.w-b.w;
            i3 += dx*dx + dy*dy + dz*dz + dw*dw;
            float xf = __ldg(lengths + e) * tscale;
            int ti = (int)xf;
            if (ti < 0) ti = 0; if (ti > TAB - 2) ti = TAB - 2;
            s_ed[warp][lane][0] = i0; s_ed[warp][lane][1] = i1;
            s_ed[warp][lane][2] = i2; s_ed[warp][lane][3] = i3;
            s_ed[warp][lane][4] = xf - (float)ti;
            s_ti[warp][lane] = ti;
        }
        __syncwarp();

        // layer 1: hidden = lane, edge pairs packed into float2
#pragma unroll
        for (int p = 0; p < 4; p++) {
            const float* e0 = s_ed[warp][2 * p];
            const float* e1 = s_ed[warp][2 * p + 1];
            float ea = silu_f(fmaf(e0[0], w1l0, fmaf(e0[1], w1l1,
                              fmaf(e0[2], w1l2, fmaf(e0[3], w1l3, bl)))));
            float eb = silu_f(fmaf(e1[0], w1l0, fmaf(e1[1], w1l1,
                              fmaf(e1[2], w1l2, fmaf(e1[3], w1l3, bl)))));
            s_e1[warp][p][lane] = make_float2(ea, eb);
        }
        __syncwarp();

        // layer 2: 32 -> 128 with f32x2 over edge pairs
        ull acc[4][4];
#pragma unroll
        for (int p = 0; p < 4; p++) { acc[p][0] = bd0; acc[p][1] = bd1; acc[p][2] = bd2; acc[p][3] = bd3; }
        const ull* e1u = reinterpret_cast<const ull*>(s_e1[warp]);
#pragma unroll 4
        for (int k = 0; k < 32; k++) {
            float4 w = wv[k * 32 + lane];
            ull wd0 = dup2(w.x), wd1 = dup2(w.y), wd2 = dup2(w.z), wd3 = dup2(w.w);
#pragma unroll
            for (int p = 0; p < 4; p++) {
                ull c = e1u[p * 32 + k];
                fma2(acc[p][0], wd0, c); fma2(acc[p][1], wd1, c);
                fma2(acc[p][2], wd2, c); fma2(acc[p][3], wd3, c);
            }
        }

        // epilogue: silu + table lerp + store
#pragma unroll
        for (int p = 0; p < 4; p++) {
            float l0, h0, l1, h1, l2, h2, l3, h3;
            unpack2(acc[p][0], l0, h0); unpack2(acc[p][1], l1, h1);
            unpack2(acc[p][2], l2, h2); unpack2(acc[p][3], l3, h3);
#pragma unroll
            for (int hh = 0; hh < 2; hh++) {
                int j = 2 * p + hh;
                int e = base + j;
                if (e < E) {
                    float e0 = hh ? h0 : l0, e1 = hh ? h1 : l1;
                    float e2 = hh ? h2 : l2, e3 = hh ? h3 : l3;
                    int ti = s_ti[warp][j];
                    float tf = s_ed[warp][j][4];
                    float4 ta = __ldg(tabv + (size_t)ti * 32 + lane);
                    float4 tb = __ldg(tabv + (size_t)(ti + 1) * 32 + lane);
                    float4 o;
                    o.x = fmaf(tf, tb.x - ta.x, ta.x) + silu_f(e0);
                    o.y = fmaf(tf, tb.y - ta.y, ta.y) + silu_f(e1);
                    o.z = fmaf(tf, tb.z - ta.z, ta.z) + silu_f(e2);
                    o.w = fmaf(tf, tb.w - ta.w, ta.w) + silu_f(e3);
                    outv[(size_t)e * 32 + lane] = o;
                }
            }
        }
        __syncwarp();
    }
}

// ---------------------------------------------------------------------------
extern "C" void kernel_launch(void* const* d_in, const int* in_sizes, int n_in,
                              void* d_out, int out_size)
{
    const float* invf      = (const float*)d_in[0];
    const float* evf       = (const float*)d_in[1];
    const int*   senders   = (const int*)  d_in[2];
    const int*   receivers = (const int*)  d_in[3];
    const float* lengths   = (const float*)d_in[5];
    const float* fi_rbf_w1 = (const float*)d_in[7];
    const float* fi_rbf_b1 = (const float*)d_in[8];
    const float* fi_rbf_w2 = (const float*)d_in[9];
    const float* fi_rbf_b2 = (const float*)d_in[10];
    const float* fi_ev_w1  = (const float*)d_in[11];
    const float* fi_ev_b1  = (const float*)d_in[12];
    const float* fi_ev_w2  = (const float*)d_in[13];
    const float* fi_ev_b2  = (const float*)d_in[14];
    const float* fe_rbf_w1 = (const float*)d_in[15];
    const float* fe_rbf_b1 = (const float*)d_in[16];
    const float* fe_rbf_w2 = (const float*)d_in[17];
    const float* fe_rbf_b2 = (const float*)d_in[18];
    const float* fe_ev_w1  = (const float*)d_in[19];
    const float* fe_ev_b1  = (const float*)d_in[20];
    const float* fe_ev_w2  = (const float*)d_in[21];
    const float* fe_ev_b2  = (const float*)d_in[22];
    const float* w_int     = (const float*)d_in[23];
    const float* b_int     = (const float*)d_in[24];

    int N = in_sizes[0] / 128;
    int E = in_sizes[5];

    float* out1 = (float*)d_out;
    float* out2 = out1 + (size_t)N * 128;
    float* fwi  = out2 + (size_t)N * 16;
    float* fwe  = fwi  + (size_t)E * 128;

    build_tab_kernel<<<dim3(TAB / 32, 2), 128>>>(
        fi_rbf_w1, fi_rbf_b1, fi_rbf_w2, fi_rbf_b2,
        fe_rbf_w1, fe_rbf_b1, fe_rbf_w2, fe_rbf_b2, 32);

    node_kernel<<<296, 256>>>(invf, evf, w_int, b_int, out1, out2, N);

    edge_kernel<<<dim3(1184, 2), 256>>>(
        evf, senders, receivers, lengths,
        fi_ev_w1, fi_ev_b1, fi_ev_w2, fi_ev_b2,
        fe_ev_w1, fe_ev_b1, fe_ev_w2, fe_ev_b2,
        fwi, fwe, E);
}

// round 7
// speedup vs baseline: 1.2814x; 1.2814x over previous
#include <cuda_runtime.h>
#include <cuda_fp16.h>

#define TAB 4096
#define FULLMASK 0xffffffffu
typedef unsigned long long ull;

// static scratch (no allocations allowed)
__device__ __half  g_htabh[2][TAB * 128];     // 2 MB: length->h tables, fp16
__device__ float4  g_einv[1000000];           // per-edge SO3 invariants
__device__ float2  g_etf[1000000];            // per-edge (tf, bitcast ti)

__device__ __forceinline__ float silu_f(float x) { return __fdividef(x, 1.0f + __expf(-x)); }
__device__ __forceinline__ ull dup2(float x) {
    ull r; unsigned u = __float_as_uint(x);
    asm("mov.b64 %0, {%1,%1};" : "=l"(r) : "r"(u)); return r;
}
__device__ __forceinline__ ull pack2(float a, float b) {
    ull r;
    asm("mov.b64 %0, {%1,%2};" : "=l"(r) : "r"(__float_as_uint(a)), "r"(__float_as_uint(b)));
    return r;
}
__device__ __forceinline__ void fma2(ull &d, ull a, ull b) {
    asm("fma.rn.f32x2 %0, %1, %2, %0;" : "+l"(d) : "l"(a), "l"(b));
}
__device__ __forceinline__ void unpack2(ull v, float &lo, float &hi) {
    unsigned a, b; asm("mov.b64 {%0,%1}, %2;" : "=r"(a), "=r"(b) : "l"(v));
    lo = __uint_as_float(a); hi = __uint_as_float(b);
}

// ---------------------------------------------------------------------------
// Length -> h(128) table builder (fp16 output). Thread f owns feature f.
// ---------------------------------------------------------------------------
__global__ void __launch_bounds__(128) build_tab_kernel(
    const float* __restrict__ w1a, const float* __restrict__ b1a,
    const float* __restrict__ w2a, const float* __restrict__ b2a,
    const float* __restrict__ w1b, const float* __restrict__ b1b,
    const float* __restrict__ w2b, const float* __restrict__ b2b,
    int rows_per_block)
{
    int filt = blockIdx.y;
    const float* w1 = filt ? w1b : w1a; const float* b1 = filt ? b1b : b1a;
    const float* w2 = filt ? w2b : w2a; const float* b2 = filt ? b2b : b2a;
    __shared__ float h1s[128];
    int f = threadIdx.x;
    float wcol[128], w1col[32];
#pragma unroll
    for (int k = 0; k < 128; k++) wcol[k] = __ldg(&w2[k * 128 + f]);
#pragma unroll
    for (int k = 0; k < 32; k++) w1col[k] = __ldg(&w1[k * 128 + f]);
    float b1f = __ldg(&b1[f]), b2f = __ldg(&b2[f]);
    const float step  = 5.0f / 31.0f;
    const float gamma = 0.5f / (step * step);
    const float dx    = 5.0f / (float)(TAB - 1);
    int r0 = blockIdx.x * rows_per_block;
    for (int rr = 0; rr < rows_per_block; rr++) {
        int row = r0 + rr;
        float x = (float)row * dx;
        float a1 = b1f;
#pragma unroll
        for (int k = 0; k < 32; k++) {
            float d = x - (float)k * step;
            a1 = fmaf(__expf(-gamma * d * d), w1col[k], a1);
        }
        h1s[f] = silu_f(a1);
        __syncthreads();
        float a2 = b2f;
#pragma unroll
        for (int k = 0; k < 128; k++) a2 = fmaf(h1s[k], wcol[k], a2);
        g_htabh[filt][(size_t)row * 128 + f] = __float2half_rn(silu_f(a2));
        __syncthreads();
    }
}

// ---------------------------------------------------------------------------
// Prep: per-edge SO3 invariants + table index/frac, computed ONCE (was done
// twice, once per filter grid, inside the old edge kernel).
// ---------------------------------------------------------------------------
__global__ void __launch_bounds__(256) prep_kernel(
    const float* __restrict__ evf, const int* __restrict__ senders,
    const int* __restrict__ receivers, const float* __restrict__ lengths, int E)
{
    const float tscale = (float)(TAB - 1) / 5.0f;
    for (int e = blockIdx.x * 256 + threadIdx.x; e < E; e += gridDim.x * 256) {
        int sN = __ldg(senders + e), rN = __ldg(receivers + e);
        const float4* As = reinterpret_cast<const float4*>(evf) + (size_t)sN * 4;
        const float4* Ar = reinterpret_cast<const float4*>(evf) + (size_t)rN * 4;
        float4 a, b; float dx, dy, dz, dw;
        float i0, i1, i2, i3;
        a = As[0]; b = Ar[0]; dx = a.x-b.x; dy = a.y-b.y; dz = a.z-b.z; dw = a.w-b.w;
        i0 = dx*dx; i1 = dy*dy + dz*dz + dw*dw;
        a = As[1]; b = Ar[1]; dx = a.x-b.x; dy = a.y-b.y; dz = a.z-b.z; dw = a.w-b.w;
        i2 = dx*dx + dy*dy + dz*dz + dw*dw;
        a = As[2]; b = Ar[2]; dx = a.x-b.x; dy = a.y-b.y; dz = a.z-b.z; dw = a.w-b.w;
        i2 += dx*dx; i3 = dy*dy + dz*dz + dw*dw;
        a = As[3]; b = Ar[3]; dx = a.x-b.x; dy = a.y-b.y; dz = a.z-b.z; dw = a.w-b.w;
        i3 += dx*dx + dy*dy + dz*dz + dw*dw;
        float xf = __ldg(lengths + e) * tscale;
        int ti = (int)xf;
        if (ti < 0) ti = 0; if (ti > TAB - 2) ti = TAB - 2;
        g_einv[e] = make_float4(i0, i1, i2, i3);
        g_etf[e]  = make_float2(xf - (float)ti, __int_as_float(ti));
    }
}

// ---------------------------------------------------------------------------
// Node kernel: 4 nodes per warp per pass (amortizes w_int LDG 2x vs before).
// ---------------------------------------------------------------------------
__global__ void __launch_bounds__(256) node_kernel(
    const float* __restrict__ invf, const float* __restrict__ evf,
    const float* __restrict__ w_int, const float* __restrict__ b_int,
    float* __restrict__ out1, float* __restrict__ out2, int N)
{
    __shared__ float xs[8][4][136];
    int warp = threadIdx.x >> 5, lane = threadIdx.x & 31;
    int ngrp = (N + 3) >> 2;
    int grp = blockIdx.x * 8 + warp;
    if (grp >= ngrp) return;
    int nbase = grp * 4;
    int o4 = (lane < 4) ? (128 + lane) : lane;
    float b0 = __ldg(b_int + lane),       b1v = __ldg(b_int + 32 + lane);
    float b2v = __ldg(b_int + 64 + lane), b3v = __ldg(b_int + 96 + lane);
    float b4v = __ldg(b_int + o4);

    float attv[4];
#pragma unroll
    for (int nd = 0; nd < 4; nd++) {
        int n = nbase + nd; if (n >= N) n = N - 1;
        float* X = xs[warp][nd];
#pragma unroll
        for (int j = 0; j < 4; j++)
            X[lane + 32 * j] = 2.0f * __ldg(invf + (size_t)n * 128 + lane + 32 * j);
        float av = 0.f, dsq = 0.f;
        if (lane < 16) { av = 2.0f * __ldg(evf + (size_t)n * 16 + lane); dsq = av * av; }
        attv[nd] = av;
        float v0 = __shfl_sync(FULLMASK, dsq, 0);
        float v1 = __shfl_sync(FULLMASK, dsq, 1) + __shfl_sync(FULLMASK, dsq, 2)
                 + __shfl_sync(FULLMASK, dsq, 3);
        float v2 = __shfl_sync(FULLMASK, dsq, 4) + __shfl_sync(FULLMASK, dsq, 5)
                 + __shfl_sync(FULLMASK, dsq, 6) + __shfl_sync(FULLMASK, dsq, 7)
                 + __shfl_sync(FULLMASK, dsq, 8);
        float v3 = __shfl_sync(FULLMASK, dsq, 9) + __shfl_sync(FULLMASK, dsq, 10)
                 + __shfl_sync(FULLMASK, dsq, 11) + __shfl_sync(FULLMASK, dsq, 12)
                 + __shfl_sync(FULLMASK, dsq, 13) + __shfl_sync(FULLMASK, dsq, 14)
                 + __shfl_sync(FULLMASK, dsq, 15);
        if (lane == 0) { X[128] = v0; X[129] = v1; X[130] = v2; X[131] = v3; }
    }
    __syncwarp();

    float a[4][5];
#pragma unroll
    for (int nd = 0; nd < 4; nd++) {
        a[nd][0] = b0; a[nd][1] = b1v; a[nd][2] = b2v; a[nd][3] = b3v; a[nd][4] = b4v;
    }
#pragma unroll 2
    for (int i = 0; i < 132; i++) {
        const float* wr = w_int + i * 132;
        float w0 = __ldg(wr + lane),      w1 = __ldg(wr + 32 + lane);
        float w2 = __ldg(wr + 64 + lane), w3 = __ldg(wr + 96 + lane);
        float w4 = __ldg(wr + o4);
#pragma unroll
        for (int nd = 0; nd < 4; nd++) {
            float x = xs[warp][nd][i];
            a[nd][0] = fmaf(x, w0, a[nd][0]); a[nd][1] = fmaf(x, w1, a[nd][1]);
            a[nd][2] = fmaf(x, w2, a[nd][2]); a[nd][3] = fmaf(x, w3, a[nd][3]);
            a[nd][4] = fmaf(x, w4, a[nd][4]);
        }
    }
#pragma unroll
    for (int nd = 0; nd < 4; nd++) {
        int n = nbase + nd;
        if (n >= N) break;
        const float* X = xs[warp][nd];
        out1[(size_t)n * 128 + lane]      = X[lane] + a[nd][0];
        out1[(size_t)n * 128 + 32 + lane] = X[32 + lane] + a[nd][1];
        out1[(size_t)n * 128 + 64 + lane] = X[64 + lane] + a[nd][2];
        out1[(size_t)n * 128 + 96 + lane] = X[96 + lane] + a[nd][3];
        float c0 = __shfl_sync(FULLMASK, a[nd][4], 0), c1 = __shfl_sync(FULLMASK, a[nd][4], 1);
        float c2 = __shfl_sync(FULLMASK, a[nd][4], 2), c3 = __shfl_sync(FULLMASK, a[nd][4], 3);
        if (lane < 16) {
            float bs = (lane == 0) ? c0 : ((lane < 4) ? c1 : ((lane < 9) ? c2 : c3));
            out2[(size_t)n * 16 + lane] = attv[nd] * (1.0f + bs);
        }
    }
}

// ---------------------------------------------------------------------------
// Edge main: blockIdx.y = filter. 8 edges per warp per pass.
// fw = tab_lerp_fp16(length) + silu(silu(inv4 @ w1 + b1) @ w2 + b2).
// Layer 2 = fma.rn.f32x2 over edge pairs; activations via LDS.128 (2 k/load).
// ---------------------------------------------------------------------------
__global__ void __launch_bounds__(256) edge_kernel(
    const float* __restrict__ fi_w1, const float* __restrict__ fi_b1,
    const float* __restrict__ fi_w2, const float* __restrict__ fi_b2,
    const float* __restrict__ fe_w1, const float* __restrict__ fe_b1,
    const float* __restrict__ fe_w2, const float* __restrict__ fe_b2,
    float* __restrict__ fwi, float* __restrict__ fwe, int E)
{
    int filt = blockIdx.y;
    const float* we1 = filt ? fe_w1 : fi_w1; const float* be1 = filt ? fe_b1 : fi_b1;
    const float* we2 = filt ? fe_w2 : fi_w2; const float* be2 = filt ? fe_b2 : fi_b2;
    float* outp = filt ? fwe : fwi;
    const __half* tabh = g_htabh[filt];

    __shared__ __align__(16) float s_we2[4096];
    __shared__ __align__(16) float2 s_e1[8][4][32];
    __shared__ __align__(16) float4 s_edv[8][8];
    __shared__ float2 s_m[8][8];

    int tid = threadIdx.x;
    for (int i = tid; i < 4096; i += 256) s_we2[i] = we2[i];
    __syncthreads();

    int warp = tid >> 5, lane = tid & 31;
    float w1l0 = __ldg(we1 + lane),      w1l1 = __ldg(we1 + 32 + lane);
    float w1l2 = __ldg(we1 + 64 + lane), w1l3 = __ldg(we1 + 96 + lane);
    float bl   = __ldg(be1 + lane);
    float4 bb  = __ldg(reinterpret_cast<const float4*>(be2) + lane);
    ull bd0 = dup2(bb.x), bd1 = dup2(bb.y), bd2 = dup2(bb.z), bd3 = dup2(bb.w);
    const float4* wv = reinterpret_cast<const float4*>(s_we2);
    float4* outv = reinterpret_cast<float4*>(outp);

    int gw = blockIdx.x * 8 + warp;
    int nwarps = gridDim.x * 8;

    for (int base = gw * 8; base < E; base += nwarps * 8) {
        if (lane < 8) {
            int e = base + lane; if (e >= E) e = E - 1;
            s_edv[warp][lane] = g_einv[e];
            s_m[warp][lane]   = g_etf[e];
        }
        __syncwarp();

        // layer 1: hidden = lane, edge pairs into float2
#pragma unroll
        for (int p = 0; p < 4; p++) {
            float4 v0 = s_edv[warp][2 * p];
            float4 v1 = s_edv[warp][2 * p + 1];
            float ea = silu_f(fmaf(v0.x, w1l0, fmaf(v0.y, w1l1,
                              fmaf(v0.z, w1l2, fmaf(v0.w, w1l3, bl)))));
            float eb = silu_f(fmaf(v1.x, w1l0, fmaf(v1.y, w1l1,
                              fmaf(v1.z, w1l2, fmaf(v1.w, w1l3, bl)))));
            s_e1[warp][p][lane] = make_float2(ea, eb);
        }
        __syncwarp();

        // layer 2: 32 -> 128, f32x2 over edge pairs, v4 activation loads
        ull acc[4][4];
#pragma unroll
        for (int p = 0; p < 4; p++) { acc[p][0] = bd0; acc[p][1] = bd1; acc[p][2] = bd2; acc[p][3] = bd3; }
        const float4* e1v = reinterpret_cast<const float4*>(s_e1[warp]);
#pragma unroll 2
        for (int k2 = 0; k2 < 16; k2++) {
            float4 wa = wv[(2 * k2) * 32 + lane];
            float4 wb = wv[(2 * k2 + 1) * 32 + lane];
            ull wa0 = dup2(wa.x), wa1 = dup2(wa.y), wa2 = dup2(wa.z), wa3 = dup2(wa.w);
            ull wb0 = dup2(wb.x), wb1 = dup2(wb.y), wb2 = dup2(wb.z), wb3 = dup2(wb.w);
#pragma unroll
            for (int p = 0; p < 4; p++) {
                float4 cc = e1v[p * 16 + k2];   // (e1[2k2].x, .y, e1[2k2+1].x, .y)
                ull c0 = pack2(cc.x, cc.y);
                ull c1 = pack2(cc.z, cc.w);
                fma2(acc[p][0], wa0, c0); fma2(acc[p][1], wa1, c0);
                fma2(acc[p][2], wa2, c0); fma2(acc[p][3], wa3, c0);
                fma2(acc[p][0], wb0, c1); fma2(acc[p][1], wb1, c1);
                fma2(acc[p][2], wb2, c1); fma2(acc[p][3], wb3, c1);
            }
        }

        // epilogue: silu + fp16 table lerp + store
#pragma unroll
        for (int p = 0; p < 4; p++) {
            float l0, h0, l1, h1, l2, h2, l3, h3;
            unpack2(acc[p][0], l0, h0); unpack2(acc[p][1], l1, h1);
            unpack2(acc[p][2], l2, h2); unpack2(acc[p][3], l3, h3);
#pragma unroll
            for (int hh = 0; hh < 2; hh++) {
                int j = 2 * p + hh;
                int e = base + j;
                if (e < E) {
                    float e0 = hh ? h0 : l0, e1 = hh ? h1 : l1;
                    float e2 = hh ? h2 : l2, e3 = hh ? h3 : l3;
                    float tf = s_m[warp][j].x;
                    int   ti = __float_as_int(s_m[warp][j].y);
                    const uint2* ta = reinterpret_cast<const uint2*>(tabh + (size_t)ti * 128) + lane;
                    uint2 ua = __ldg(ta);
                    uint2 ub = __ldg(ta + 32);   // next row (+128 halfs = +32 uint2)
                    float2 a01 = __half22float2(*reinterpret_cast<__half2*>(&ua.x));
                    float2 a23 = __half22float2(*reinterpret_cast<__half2*>(&ua.y));
                    float2 b01 = __half22float2(*reinterpret_cast<__half2*>(&ub.x));
                    float2 b23 = __half22float2(*reinterpret_cast<__half2*>(&ub.y));
                    float4 o;
                    o.x = fmaf(tf, b01.x - a01.x, a01.x) + silu_f(e0);
                    o.y = fmaf(tf, b01.y - a01.y, a01.y) + silu_f(e1);
                    o.z = fmaf(tf, b23.x - a23.x, a23.x) + silu_f(e2);
                    o.w = fmaf(tf, b23.y - a23.y, a23.y) + silu_f(e3);
                    outv[(size_t)e * 32 + lane] = o;
                }
            }
        }
        __syncwarp();
    }
}

// ---------------------------------------------------------------------------
extern "C" void kernel_launch(void* const* d_in, const int* in_sizes, int n_in,
                              void* d_out, int out_size)
{
    const float* invf      = (const float*)d_in[0];
    const float* evf       = (const float*)d_in[1];
    const int*   senders   = (const int*)  d_in[2];
    const int*   receivers = (const int*)  d_in[3];
    const float* lengths   = (const float*)d_in[5];
    const float* fi_rbf_w1 = (const float*)d_in[7];
    const float* fi_rbf_b1 = (const float*)d_in[8];
    const float* fi_rbf_w2 = (const float*)d_in[9];
    const float* fi_rbf_b2 = (const float*)d_in[10];
    const float* fi_ev_w1  = (const float*)d_in[11];
    const float* fi_ev_b1  = (const float*)d_in[12];
    const float* fi_ev_w2  = (const float*)d_in[13];
    const float* fi_ev_b2  = (const float*)d_in[14];
    const float* fe_rbf_w1 = (const float*)d_in[15];
    const float* fe_rbf_b1 = (const float*)d_in[16];
    const float* fe_rbf_w2 = (const float*)d_in[17];
    const float* fe_rbf_b2 = (const float*)d_in[18];
    const float* fe_ev_w1  = (const float*)d_in[19];
    const float* fe_ev_b1  = (const float*)d_in[20];
    const float* fe_ev_w2  = (const float*)d_in[21];
    const float* fe_ev_b2  = (const float*)d_in[22];
    const float* w_int     = (const float*)d_in[23];
    const float* b_int     = (const float*)d_in[24];

    int N = in_sizes[0] / 128;
    int E = in_sizes[5];

    float* out1 = (float*)d_out;
    float* out2 = out1 + (size_t)N * 128;
    float* fwi  = out2 + (size_t)N * 16;
    float* fwe  = fwi  + (size_t)E * 128;

    build_tab_kernel<<<dim3(128, 2), 128>>>(
        fi_rbf_w1, fi_rbf_b1, fi_rbf_w2, fi_rbf_b2,
        fe_rbf_w1, fe_rbf_b1, fe_rbf_w2, fe_rbf_b2, 32);

    prep_kernel<<<(E + 255) / 256, 256>>>(evf, senders, receivers, lengths, E);

    node_kernel<<<(((N + 3) / 4) + 7) / 8, 256>>>(invf, evf, w_int, b_int, out1, out2, N);

    edge_kernel<<<dim3(1184, 2), 256>>>(
        fi_ev_w1, fi_ev_b1, fi_ev_w2, fi_ev_b2,
        fe_ev_w1, fe_ev_b1, fe_ev_w2, fe_ev_b2,
        fwi, fwe, E);
}